// round 13
// baseline (speedup 1.0000x reference)
#include <cuda_runtime.h>
#include <cuda_bf16.h>

#define MARGIN 0.5f
#define EPS 1e-6f
#define C_MAX 1024          // class ids live in [0,1000); padded
#define NSM 148
#define CTHREADS 1024       // one block per SM, 32 warps

// Allocation-free scratch; last finishing block resets for graph replays.
__device__ double g_sum = 0.0;
__device__ unsigned int g_count = 0u;
__device__ unsigned int g_ticket = 0u;
__device__ int d_cstart[C_MAX];   // zero-init: absent classes have s==e==0
__device__ int d_cend[C_MAX];

__device__ __forceinline__ float dsq(const float4 a, const float4 b)
{
    float d0 = a.x - b.x + EPS;
    float d1 = a.y - b.y + EPS;
    float d2 = a.z - b.z + EPS;
    float d3 = a.w - b.w + EPS;
    return fmaf(d0, d0, fmaf(d1, d1, fmaf(d2, d2, d3 * d3)));
}

// Triplets are contiguous per class (verified: R10 passed with this assumption).
__global__ void bounds_kernel(const int* __restrict__ a_idx,
                              const int* __restrict__ labels, int T)
{
    const int t = blockIdx.x * blockDim.x + threadIdx.x;
    if (t >= T) return;
    const int c = labels[a_idx[t]];
    if (c < 0 || c >= C_MAX) return;
    if (t == 0 || labels[a_idx[t - 1]] != c) d_cstart[c] = t;
    if (t == T - 1) d_cend[c] = T;
    else if (labels[a_idx[t + 1]] != c) d_cend[c] = t + 1;
}

// One persistent block per SM; blocks pull whole classes from a ticket queue.
// Phase 1 touches the class's rows (loads them into this SM's L1); phase 2 is
// the proven gather loop — anchors + positives then hit L1, negatives stream.
__global__ void __launch_bounds__(CTHREADS, 1) class_kernel(
    const float* __restrict__ emb,
    const int* __restrict__ a_idx,
    const int* __restrict__ p_idx,
    const int* __restrict__ n_idx,
    int T,
    float* __restrict__ out)
{
    __shared__ int s_class;
    __shared__ float warp_vals[CTHREADS / 32];

    const int tid = threadIdx.x;
    const int wid = tid >> 5;
    const int lane = tid & 31;
    const int h = lane >> 4;     // half-warp id
    const int sl = lane & 15;    // sublane within half

    float acc = 0.0f;

    while (true) {
        if (tid == 0) s_class = (int)atomicAdd(&g_ticket, 1u);
        __syncthreads();
        const int c = s_class;
        __syncthreads();          // all threads consumed s_class before next write
        if (c >= C_MAX) break;

        const int s = d_cstart[c];
        const int e = d_cend[c];
        if (s >= e || e > T) continue;

        // ---- Phase 1: touch all class rows (populate L1). One warp per row. ----
        for (int r = s + wid; r < e; r += CTHREADS / 32) {
            const int g = __ldg(a_idx + r);
            const float4 v = __ldg(reinterpret_cast<const float4*>(emb + (size_t)g * 128) + lane);
            asm volatile("" :: "f"(v.x), "f"(v.y), "f"(v.z), "f"(v.w));
        }
        __syncthreads();

        // ---- Phase 2: proven loop body over this class's triplets. ----
        for (int t0 = s + wid * 4; t0 < e; t0 += (CTHREADS / 32) * 4) {
            const int tA = t0 + h;
            const int tB = t0 + 2 + h;
            const bool vA = (tA < e);
            const bool vB = (tB < e);
            const int cA = vA ? tA : s;
            const int cB = vB ? tB : s;

            const int iaA = a_idx[cA], ipA = p_idx[cA], inA = n_idx[cA];
            const int iaB = a_idx[cB], ipB = p_idx[cB], inB = n_idx[cB];

            const float4* raA = reinterpret_cast<const float4*>(emb + (size_t)iaA * 128) + sl;
            const float4* rpA = reinterpret_cast<const float4*>(emb + (size_t)ipA * 128) + sl;
            const float4* rnA = reinterpret_cast<const float4*>(emb + (size_t)inA * 128) + sl;
            const float4* raB = reinterpret_cast<const float4*>(emb + (size_t)iaB * 128) + sl;
            const float4* rpB = reinterpret_cast<const float4*>(emb + (size_t)ipB * 128) + sl;
            const float4* rnB = reinterpret_cast<const float4*>(emb + (size_t)inB * 128) + sl;

            const float4 aA0 = __ldg(raA), aA1 = __ldg(raA + 16);
            const float4 pA0 = __ldg(rpA), pA1 = __ldg(rpA + 16);
            const float4 nA0 = __ldg(rnA), nA1 = __ldg(rnA + 16);
            const float4 aB0 = __ldg(raB), aB1 = __ldg(raB + 16);
            const float4 pB0 = __ldg(rpB), pB1 = __ldg(rpB + 16);
            const float4 nB0 = __ldg(rnB), nB1 = __ldg(rnB + 16);

            float spA = dsq(aA0, pA0) + dsq(aA1, pA1);
            float snA = dsq(aA0, nA0) + dsq(aA1, nA1);
            float spB = dsq(aB0, pB0) + dsq(aB1, pB1);
            float snB = dsq(aB0, nB0) + dsq(aB1, nB1);

            #pragma unroll
            for (int off = 8; off > 0; off >>= 1) {
                spA += __shfl_down_sync(0xFFFFFFFFu, spA, off, 16);
                snA += __shfl_down_sync(0xFFFFFFFFu, snA, off, 16);
                spB += __shfl_down_sync(0xFFFFFFFFu, spB, off, 16);
                snB += __shfl_down_sync(0xFFFFFFFFu, snB, off, 16);
            }

            if (sl == 0) {
                if (vA) acc += fmaxf(sqrtf(spA) - sqrtf(snA) + MARGIN, 0.0f);
                if (vB) acc += fmaxf(sqrtf(spB) - sqrtf(snB) + MARGIN, 0.0f);
            }
        }
        __syncthreads();
    }

    // ---- Block reduce (32 warps) + global accumulate + fused finalize ----
    #pragma unroll
    for (int off = 16; off > 0; off >>= 1)
        acc += __shfl_down_sync(0xFFFFFFFFu, acc, off);
    if (lane == 0) warp_vals[wid] = acc;
    __syncthreads();

    if (wid == 0) {
        float v = warp_vals[lane];
        #pragma unroll
        for (int off = 16; off > 0; off >>= 1)
            v += __shfl_down_sync(0xFFFFFFFFu, v, off);

        if (lane == 0) {
            atomicAdd(&g_sum, (double)v);
            __threadfence();
            const unsigned int prev = atomicAdd(&g_count, 1u);
            if (prev == gridDim.x - 1) {
                const double total = atomicAdd(&g_sum, 0.0);
                out[0] = (float)(total / (double)T);
                g_sum = 0.0;
                atomicExch(&g_ticket, 0u);
                __threadfence();
                atomicExch(&g_count, 0u);
            }
        }
    }
}

extern "C" void kernel_launch(void* const* d_in, const int* in_sizes, int n_in,
                              void* d_out, int out_size) {
    const float* emb   = (const float*)d_in[0];
    const int* labels  = (const int*)d_in[1];
    const int* a_idx   = (const int*)d_in[2];
    const int* p_idx   = (const int*)d_in[3];
    const int* n_idx   = (const int*)d_in[4];
    float* out         = (float*)d_out;

    const int T = in_sizes[2];

    bounds_kernel<<<(T + 255) / 256, 256>>>(a_idx, labels, T);
    class_kernel<<<NSM, CTHREADS>>>(emb, a_idx, p_idx, n_idx, T, out);
}

// round 14
// speedup vs baseline: 1.5091x; 1.5091x over previous
#include <cuda_runtime.h>
#include <cuda_bf16.h>

#define MARGIN 0.5f
#define EPS 1e-6f
#define WARPS_PER_BLOCK 8
#define THREADS (WARPS_PER_BLOCK * 32)
#define NSM 148
#define BLOCKS_PER_SM 4

// Allocation-free scratch; last finishing block resets for graph replays.
__device__ double g_sum = 0.0;
__device__ unsigned int g_count = 0u;

__device__ __forceinline__ float dsq(const float4 a, const float4 b)
{
    float d0 = a.x - b.x + EPS;
    float d1 = a.y - b.y + EPS;
    float d2 = a.z - b.z + EPS;
    float d3 = a.w - b.w + EPS;
    return fmaf(d0, d0, fmaf(d1, d1, fmaf(d2, d2, d3 * d3)));
}

// Paired reduction over a 16-lane half: on entry each lane holds partial sp
// and sn. One exchange folds them into a single butterfly value (low 8 lanes
// carry sp, high 8 carry sn), 3 xor steps finish both sums, both halves take
// their sqrt in parallel, one last exchange pairs d_pos with d_neg.
// Returns relu(d_pos - d_neg + MARGIN) valid on lanes with (lane&15)==0.
__device__ __forceinline__ float reduce_pair(float sp, float sn, int lane)
{
    const unsigned full = 0xFFFFFFFFu;
    const bool hi = (lane & 8) != 0;
    float send = hi ? sp : sn;
    float recv = __shfl_xor_sync(full, send, 8, 16);
    float v = (hi ? sn : sp) + recv;      // lo lanes: sp pair-sum, hi lanes: sn
    v += __shfl_xor_sync(full, v, 4, 16);
    v += __shfl_xor_sync(full, v, 2, 16);
    v += __shfl_xor_sync(full, v, 1, 16);
    float d = sqrtf(v);                   // lo: d_pos, hi: d_neg (all lanes)
    float o = __shfl_xor_sync(full, d, 8, 16);
    return fmaxf(d - o + MARGIN, 0.0f);   // valid where !hi; read at sl==0
}

// Half-warp per triplet, dense 256B addressing, 12 gathers in flight,
// SM-affinity block remap, paired 5-shuffle reduction.
__global__ void __launch_bounds__(THREADS, 4) triplet_kernel(
    const float* __restrict__ emb,
    const int* __restrict__ a_idx,
    const int* __restrict__ p_idx,
    const int* __restrict__ n_idx,
    int T,
    float* __restrict__ out)
{
    const int lane = threadIdx.x & 31;
    const int h = lane >> 4;      // which half-warp
    const int s = lane & 15;      // sublane within half
    const int warp_in_block = threadIdx.x >> 5;

    // Virtual block id: co-resident blocks get consecutive vb.
    const int vb = (blockIdx.x % NSM) * BLOCKS_PER_SM + (blockIdx.x / NSM);
    const int gwarp = vb * WARPS_PER_BLOCK + warp_in_block;
    const int nwarps = gridDim.x * WARPS_PER_BLOCK;

    float acc = 0.0f;

    for (int t0 = gwarp * 4; t0 < T; t0 += nwarps * 4) {
        const int tA = t0 + h;          // group A triplets: t0, t0+1
        const int tB = t0 + 2 + h;      // group B triplets: t0+2, t0+3
        const bool vA = (tA < T);
        const bool vB = (tB < T);
        const int cA = vA ? tA : 0;
        const int cB = vB ? tB : 0;

        const int iaA = a_idx[cA], ipA = p_idx[cA], inA = n_idx[cA];
        const int iaB = a_idx[cB], ipB = p_idx[cB], inB = n_idx[cB];

        const float4* raA = reinterpret_cast<const float4*>(emb + (size_t)iaA * 128) + s;
        const float4* rpA = reinterpret_cast<const float4*>(emb + (size_t)ipA * 128) + s;
        const float4* rnA = reinterpret_cast<const float4*>(emb + (size_t)inA * 128) + s;
        const float4* raB = reinterpret_cast<const float4*>(emb + (size_t)iaB * 128) + s;
        const float4* rpB = reinterpret_cast<const float4*>(emb + (size_t)ipB * 128) + s;
        const float4* rnB = reinterpret_cast<const float4*>(emb + (size_t)inB * 128) + s;

        // Issue all 12 loads up front (each covers two dense 256B blocks).
        const float4 aA0 = __ldg(raA),     aA1 = __ldg(raA + 16);
        const float4 pA0 = __ldg(rpA),     pA1 = __ldg(rpA + 16);
        const float4 nA0 = __ldg(rnA),     nA1 = __ldg(rnA + 16);
        const float4 aB0 = __ldg(raB),     aB1 = __ldg(raB + 16);
        const float4 pB0 = __ldg(rpB),     pB1 = __ldg(rpB + 16);
        const float4 nB0 = __ldg(rnB),     nB1 = __ldg(rnB + 16);

        float spA = dsq(aA0, pA0) + dsq(aA1, pA1);
        float snA = dsq(aA0, nA0) + dsq(aA1, nA1);
        float spB = dsq(aB0, pB0) + dsq(aB1, pB1);
        float snB = dsq(aB0, nB0) + dsq(aB1, nB1);

        const float rA = reduce_pair(spA, snA, lane);
        const float rB = reduce_pair(spB, snB, lane);

        if (s == 0) {
            if (vA) acc += rA;
            if (vB) acc += rB;
        }
    }

    // Full warp reduce of acc (nonzero in lanes 0 and 16).
    #pragma unroll
    for (int off = 16; off > 0; off >>= 1)
        acc += __shfl_down_sync(0xFFFFFFFFu, acc, off);

    __shared__ float warp_vals[WARPS_PER_BLOCK];
    if (lane == 0) warp_vals[warp_in_block] = acc;
    __syncthreads();

    if (warp_in_block == 0) {
        float v = (lane < WARPS_PER_BLOCK) ? warp_vals[lane] : 0.0f;
        #pragma unroll
        for (int off = 4; off > 0; off >>= 1)
            v += __shfl_down_sync(0xFFFFFFFFu, v, off);

        if (lane == 0) {
            atomicAdd(&g_sum, (double)v);
            __threadfence();
            unsigned int prev = atomicAdd(&g_count, 1u);
            if (prev == gridDim.x - 1) {
                double total = atomicAdd(&g_sum, 0.0);
                out[0] = (float)(total / (double)T);
                g_sum = 0.0;
                __threadfence();
                atomicExch(&g_count, 0u);
            }
        }
    }
}

extern "C" void kernel_launch(void* const* d_in, const int* in_sizes, int n_in,
                              void* d_out, int out_size) {
    const float* emb   = (const float*)d_in[0];
    // d_in[1] = labels (unused; mining is precomputed in the reference inputs)
    const int* a_idx   = (const int*)d_in[2];
    const int* p_idx   = (const int*)d_in[3];
    const int* n_idx   = (const int*)d_in[4];
    float* out         = (float*)d_out;

    const int T = in_sizes[2];

    // Exactly 4 resident blocks per SM on 148 SMs (the remap assumes it).
    int blocks = NSM * BLOCKS_PER_SM;
    int max_blocks = (T + WARPS_PER_BLOCK * 4 - 1) / (WARPS_PER_BLOCK * 4);
    if (blocks > max_blocks) blocks = max_blocks;
    if (blocks < 1) blocks = 1;

    triplet_kernel<<<blocks, THREADS>>>(emb, a_idx, p_idx, n_idx, T, out);
}

// round 15
// speedup vs baseline: 1.6019x; 1.0615x over previous
#include <cuda_runtime.h>
#include <cuda_bf16.h>

#define MARGIN 0.5f
#define EPS 1e-6f
#define WARPS_PER_BLOCK 8
#define THREADS (WARPS_PER_BLOCK * 32)
#define NSM 148
#define BLOCKS_PER_SM 4

// Allocation-free scratch; last finishing block resets for graph replays.
__device__ double g_sum = 0.0;
__device__ unsigned int g_count = 0u;

__device__ __forceinline__ float dsq(const float4 a, const float4 b)
{
    float d0 = a.x - b.x + EPS;
    float d1 = a.y - b.y + EPS;
    float d2 = a.z - b.z + EPS;
    float d3 = a.w - b.w + EPS;
    return fmaf(d0, d0, fmaf(d1, d1, fmaf(d2, d2, d3 * d3)));
}

// Paired reduction over a 16-lane half (5 shuffles for both sums + both sqrts).
// Returns relu(d_pos - d_neg + MARGIN) valid on lanes with (lane&15)==0.
__device__ __forceinline__ float reduce_pair(float sp, float sn, int lane)
{
    const unsigned full = 0xFFFFFFFFu;
    const bool hi = (lane & 8) != 0;
    float send = hi ? sp : sn;
    float recv = __shfl_xor_sync(full, send, 8, 16);
    float v = (hi ? sn : sp) + recv;      // lo lanes: sp pair-sum, hi lanes: sn
    v += __shfl_xor_sync(full, v, 4, 16);
    v += __shfl_xor_sync(full, v, 2, 16);
    v += __shfl_xor_sync(full, v, 1, 16);
    float d = sqrtf(v);                   // lo: d_pos, hi: d_neg
    float o = __shfl_xor_sync(full, d, 8, 16);
    return fmaxf(d - o + MARGIN, 0.0f);   // valid where !hi; read at sl==0
}

// The proven group-of-4 body (half-warp per triplet, dense 256B addressing,
// 12 gathers in flight).
__device__ __forceinline__ float group4(
    const float* __restrict__ emb,
    const int* __restrict__ a_idx,
    const int* __restrict__ p_idx,
    const int* __restrict__ n_idx,
    int t0, int T, int h, int s, int lane)
{
    const int tA = t0 + h;          // triplets t0, t0+1
    const int tB = t0 + 2 + h;      // triplets t0+2, t0+3
    const bool vA = (tA < T);
    const bool vB = (tB < T);
    const int cA = vA ? tA : 0;
    const int cB = vB ? tB : 0;

    const int iaA = a_idx[cA], ipA = p_idx[cA], inA = n_idx[cA];
    const int iaB = a_idx[cB], ipB = p_idx[cB], inB = n_idx[cB];

    const float4* raA = reinterpret_cast<const float4*>(emb + (size_t)iaA * 128) + s;
    const float4* rpA = reinterpret_cast<const float4*>(emb + (size_t)ipA * 128) + s;
    const float4* rnA = reinterpret_cast<const float4*>(emb + (size_t)inA * 128) + s;
    const float4* raB = reinterpret_cast<const float4*>(emb + (size_t)iaB * 128) + s;
    const float4* rpB = reinterpret_cast<const float4*>(emb + (size_t)ipB * 128) + s;
    const float4* rnB = reinterpret_cast<const float4*>(emb + (size_t)inB * 128) + s;

    const float4 aA0 = __ldg(raA), aA1 = __ldg(raA + 16);
    const float4 pA0 = __ldg(rpA), pA1 = __ldg(rpA + 16);
    const float4 nA0 = __ldg(rnA), nA1 = __ldg(rnA + 16);
    const float4 aB0 = __ldg(raB), aB1 = __ldg(raB + 16);
    const float4 pB0 = __ldg(rpB), pB1 = __ldg(rpB + 16);
    const float4 nB0 = __ldg(rnB), nB1 = __ldg(rnB + 16);

    float spA = dsq(aA0, pA0) + dsq(aA1, pA1);
    float snA = dsq(aA0, nA0) + dsq(aA1, nA1);
    float spB = dsq(aB0, pB0) + dsq(aB1, pB1);
    float snB = dsq(aB0, nB0) + dsq(aB1, nB1);

    const float rA = reduce_pair(spA, snA, lane);
    const float rB = reduce_pair(spB, snB, lane);

    float r = 0.0f;
    if ((lane & 15) == 0) {
        if (vA) r += rA;
        if (vB) r += rB;
    }
    return r;
}

// Grid-stride over 8-triplet super-groups: each SM's 32 warps cover 256
// consecutive triplets per stride step (~one full class), so positive-row
// gathers hit rows co-loaded as anchors on the same SM -> L1 hits.
__global__ void __launch_bounds__(THREADS, 4) triplet_kernel(
    const float* __restrict__ emb,
    const int* __restrict__ a_idx,
    const int* __restrict__ p_idx,
    const int* __restrict__ n_idx,
    int T,
    float* __restrict__ out)
{
    const int lane = threadIdx.x & 31;
    const int h = lane >> 4;
    const int s = lane & 15;
    const int warp_in_block = threadIdx.x >> 5;

    // Virtual block id: co-resident blocks (bid % 148 equal) get consecutive vb.
    const int vb = (blockIdx.x % NSM) * BLOCKS_PER_SM + (blockIdx.x / NSM);
    const int gwarp = vb * WARPS_PER_BLOCK + warp_in_block;
    const int nwarps = gridDim.x * WARPS_PER_BLOCK;

    float acc = 0.0f;

    for (int base = gwarp * 8; base < T; base += nwarps * 8) {
        acc += group4(emb, a_idx, p_idx, n_idx, base,     T, h, s, lane);
        if (base + 4 < T)
            acc += group4(emb, a_idx, p_idx, n_idx, base + 4, T, h, s, lane);
    }

    // Full warp reduce of acc (nonzero in lanes 0 and 16).
    #pragma unroll
    for (int off = 16; off > 0; off >>= 1)
        acc += __shfl_down_sync(0xFFFFFFFFu, acc, off);

    __shared__ float warp_vals[WARPS_PER_BLOCK];
    if (lane == 0) warp_vals[warp_in_block] = acc;
    __syncthreads();

    if (warp_in_block == 0) {
        float v = (lane < WARPS_PER_BLOCK) ? warp_vals[lane] : 0.0f;
        #pragma unroll
        for (int off = 4; off > 0; off >>= 1)
            v += __shfl_down_sync(0xFFFFFFFFu, v, off);

        if (lane == 0) {
            atomicAdd(&g_sum, (double)v);
            __threadfence();
            unsigned int prev = atomicAdd(&g_count, 1u);
            if (prev == gridDim.x - 1) {
                double total = atomicAdd(&g_sum, 0.0);
                out[0] = (float)(total / (double)T);
                g_sum = 0.0;
                __threadfence();
                atomicExch(&g_count, 0u);
            }
        }
    }
}

extern "C" void kernel_launch(void* const* d_in, const int* in_sizes, int n_in,
                              void* d_out, int out_size) {
    const float* emb   = (const float*)d_in[0];
    // d_in[1] = labels (unused; mining is precomputed in the reference inputs)
    const int* a_idx   = (const int*)d_in[2];
    const int* p_idx   = (const int*)d_in[3];
    const int* n_idx   = (const int*)d_in[4];
    float* out         = (float*)d_out;

    const int T = in_sizes[2];

    // Exactly 4 resident blocks per SM on 148 SMs (the remap assumes it).
    int blocks = NSM * BLOCKS_PER_SM;
    int max_blocks = (T + WARPS_PER_BLOCK * 8 - 1) / (WARPS_PER_BLOCK * 8);
    if (blocks > max_blocks) blocks = max_blocks;
    if (blocks < 1) blocks = 1;

    triplet_kernel<<<blocks, THREADS>>>(emb, a_idx, p_idx, n_idx, T, out);
}